// round 15
// baseline (speedup 1.0000x reference)
#include <cuda_runtime.h>
#include <cuda_bf16.h>
#include <math.h>
#include <stdint.h>

#define NN    10000
#define E0    160000
#define ET    (E0 + NN)
#define H     8
#define HID   256
#define NC    40
#define EPSV  1e-5f

// ---------------- scratch ----------------
__device__ float    g_h0[(size_t)NN * HID];          // layer0 features; reused as classifier scratch
__device__ float    g_hbn0[(size_t)NN * HID];
__device__ float    g_acc[(size_t)NN * HID];
__device__ float    g_ssrc[NN * H];
__device__ float    g_sdst[NN * H];
__device__ float    g_bnsum[HID];
__device__ float    g_bnsq[HID];
__device__ float    g_wsrc[256 * H];                 // W1^T a_src1 [k][h]
__device__ float    g_wdst[256 * H];
// edge sort by dst
__device__ int      g_cnt[NN];
__device__ int      g_start[NN + 1];
__device__ int      g_cur[NN];
__device__ int      g_sorted[ET];
// bf16 split operands: A side stored dedup [hi | lo] (2*KH); B side [hi | hi | lo] (3*KH)
__device__ __nv_bfloat16 g_xsp [(size_t)NN * 512];    // x split  (KH=256)
__device__ __nv_bfloat16 g_a1sp[(size_t)NN * 4096];   // agg1 out (KH=2048)
__device__ __nv_bfloat16 g_c1sp[(size_t)NN * 512];    // bn1 out  (KH=256)
__device__ __nv_bfloat16 g_w0sp[(size_t)256 * 768];
__device__ __nv_bfloat16 g_w1sp[(size_t)256 * 6144];
__device__ __nv_bfloat16 g_wcsp[(size_t)128 * 768];   // padded Wc^T

// ---------------- helpers ----------------
__device__ __forceinline__ uint32_t smem_u32(const void* p) {
    uint32_t a;
    asm("{ .reg .u64 t; cvta.to.shared.u64 t, %1; cvt.u32.u64 %0, t; }" : "=r"(a) : "l"(p));
    return a;
}
__device__ __forceinline__ void cp16(uint32_t dst, const void* src, bool pred) {
    int sz = pred ? 16 : 0;
    asm volatile("cp.async.cg.shared.global [%0], [%1], 16, %2;"
                 :: "r"(dst), "l"(src), "r"(sz));
}
__device__ __forceinline__ void ldm_x4(uint32_t* r, uint32_t addr) {
    asm volatile("ldmatrix.sync.aligned.m8n8.x4.shared.b16 {%0,%1,%2,%3}, [%4];"
                 : "=r"(r[0]), "=r"(r[1]), "=r"(r[2]), "=r"(r[3]) : "r"(addr));
}
__device__ __forceinline__ void mma16816(float* c, const uint32_t* a, uint32_t b0, uint32_t b1) {
    asm volatile("mma.sync.aligned.m16n8k16.row.col.f32.bf16.bf16.f32 "
                 "{%0,%1,%2,%3}, {%4,%5,%6,%7}, {%8,%9}, {%0,%1,%2,%3};"
                 : "+f"(c[0]), "+f"(c[1]), "+f"(c[2]), "+f"(c[3])
                 : "r"(a[0]), "r"(a[1]), "r"(a[2]), "r"(a[3]), "r"(b0), "r"(b1));
}
__device__ __forceinline__ unsigned fflip(float f) {
    unsigned u = __float_as_uint(f);
    return u ^ ((u & 0x80000000u) ? 0xFFFFFFFFu : 0x80000000u);
}
__device__ __forceinline__ float funflip(unsigned u) {
    return __uint_as_float(u ^ ((u & 0x80000000u) ? 0x80000000u : 0xFFFFFFFFu));
}
__device__ __forceinline__ int edge_src(const int* __restrict__ ei, int e) {
    return (e < E0) ? ei[e] : e - E0;
}

// ---------------- split conversion kernels ----------------
// A side: [n][256] fp32 -> [n][512] bf16 [hi | lo]
__global__ void split_a_kernel(const float* __restrict__ src, __nv_bfloat16* __restrict__ dst,
                               int rows) {
    int i = blockIdx.x * blockDim.x + threadIdx.x;
    if (i >= rows * 256) return;
    int r = i >> 8, k = i & 255;
    float v = src[i];
    __nv_bfloat16 h = __float2bfloat16(v);
    __nv_bfloat16 l = __float2bfloat16(v - __bfloat162float(h));
    __nv_bfloat16* p = dst + (size_t)r * 512;
    p[k] = h; p[256 + k] = l;
}
// W0 [256][No] -> [No][768] bf16 [hi | hi | lo]
__global__ void split_bT_kernel(const float* __restrict__ W, __nv_bfloat16* __restrict__ dst,
                                int No) {
    int i = blockIdx.x * blockDim.x + threadIdx.x;
    if (i >= 256 * No) return;
    int k = i / No, n = i % No;
    float v = W[i];
    __nv_bfloat16 h = __float2bfloat16(v);
    __nv_bfloat16 l = __float2bfloat16(v - __bfloat162float(h));
    __nv_bfloat16* p = dst + (size_t)n * 768;
    p[k] = h; p[256 + k] = h; p[512 + k] = l;
}
// W1 [256][2048] -> w1sp [c][j=h*256+k] = W1[k][h*256+c], [hi|hi|lo] over KH=2048
__global__ void split_b1_kernel(const float* __restrict__ W1) {
    int i = blockIdx.x * blockDim.x + threadIdx.x;
    if (i >= 256 * 2048) return;
    int c = i >> 11, j = i & 2047;
    int hh = j >> 8, k = j & 255;
    float v = W1[(size_t)k * 2048 + hh * 256 + c];
    __nv_bfloat16 h = __float2bfloat16(v);
    __nv_bfloat16 l = __float2bfloat16(v - __bfloat162float(h));
    __nv_bfloat16* p = g_w1sp + (size_t)c * 6144;
    p[j] = h; p[2048 + j] = h; p[4096 + j] = l;
}
// Wc [256][40] -> wcsp [n=0..127][768], zero-padded rows n>=40
__global__ void split_bc_kernel(const float* __restrict__ Wc) {
    int i = blockIdx.x * blockDim.x + threadIdx.x;
    if (i >= 128 * 256) return;
    int n = i >> 8, k = i & 255;
    float v = (n < NC) ? Wc[(size_t)k * NC + n] : 0.f;
    __nv_bfloat16 h = __float2bfloat16(v);
    __nv_bfloat16 l = __float2bfloat16(v - __bfloat162float(h));
    __nv_bfloat16* p = g_wcsp + (size_t)n * 768;
    p[k] = h; p[256 + k] = h; p[512 + k] = l;
}
__global__ void watt_kernel(const float* __restrict__ W1, const float* __restrict__ as1,
                            const float* __restrict__ ad1) {
    int g = (blockIdx.x * blockDim.x + threadIdx.x) >> 5;
    int lane = threadIdx.x & 31;
    if (g >= 256 * H) return;
    int k = g >> 3, hh = g & 7;
    const float* wr = W1 + (size_t)k * 2048 + hh * 256;
    const float* a1 = as1 + hh * 256;
    const float* a2 = ad1 + hh * 256;
    float s1 = 0.f, s2 = 0.f;
    for (int j = lane; j < 256; j += 32) { float w = wr[j]; s1 += w * a1[j]; s2 += w * a2[j]; }
    #pragma unroll
    for (int o = 16; o; o >>= 1) {
        s1 += __shfl_down_sync(0xffffffffu, s1, o);
        s2 += __shfl_down_sync(0xffffffffu, s2, o);
    }
    if (lane == 0) { g_wsrc[k * 8 + hh] = s1; g_wdst[k * 8 + hh] = s2; }
}

// ---------------- edge counting sort by dst ----------------
__global__ void zero_cnt_kernel() {
    int i = blockIdx.x * blockDim.x + threadIdx.x;
    if (i < NN) g_cnt[i] = 0;
}
__global__ void hist_kernel(const int* __restrict__ ei) {
    int e = blockIdx.x * blockDim.x + threadIdx.x;
    if (e >= ET) return;
    int d = (e < E0) ? ei[E0 + e] : e - E0;
    atomicAdd(&g_cnt[d], 1);
}
__global__ void scan_kernel() {
    __shared__ int wsum[32];
    int t = threadIdx.x, lane = t & 31, w = t >> 5;
    int base = t * 10;
    int loc[10]; int s = 0;
    #pragma unroll
    for (int i = 0; i < 10; i++) {
        int idx = base + i;
        int c = (idx < NN) ? g_cnt[idx] : 0;
        loc[i] = c; s += c;
    }
    // exclusive scan of per-thread sums: warp shfl + warp-sums pass
    int incl = s;
    #pragma unroll
    for (int o = 1; o < 32; o <<= 1) {
        int v = __shfl_up_sync(0xffffffffu, incl, o);
        if (lane >= o) incl += v;
    }
    if (lane == 31) wsum[w] = incl;
    __syncthreads();
    if (w == 0) {
        int v = (lane < 32) ? wsum[lane] : 0;
        int iv = v;
        #pragma unroll
        for (int o = 1; o < 32; o <<= 1) {
            int u = __shfl_up_sync(0xffffffffu, iv, o);
            if (lane >= o) iv += u;
        }
        wsum[lane] = iv - v;   // exclusive
    }
    __syncthreads();
    int run = wsum[w] + incl - s;   // exclusive prefix for this thread
    #pragma unroll
    for (int i = 0; i < 10; i++) {
        int idx = base + i;
        if (idx < NN) { g_start[idx] = run; g_cur[idx] = run; run += loc[i]; }
    }
    if (t == 1023) g_start[NN] = run;
}
__global__ void scatter_kernel(const int* __restrict__ ei) {
    int e = blockIdx.x * blockDim.x + threadIdx.x;
    if (e >= ET) return;
    int d = (e < E0) ? ei[E0 + e] : e - E0;
    int pos = atomicAdd(&g_cur[d], 1);
    g_sorted[pos] = e;
}

// ---------------- bf16 mma.sync split GEMM, 4-stage cp.async pipeline ----------------
// Computes C = Ah@Bh^T + Al@Bh^T + Ah@Bl^T with A stored dedup [hi|lo] (2*KH)
// and Bt stored [hi|hi|lo] (3*KH). Tile 128x128, BK=32, 8 warps (4Mx2N).
#define BK     32
#define SROWB  80
#define STG_B  (128 * SROWB * 2)
#define GSMEM  (4 * STG_B)
__global__ __launch_bounds__(256, 1)
void mma_gemm_kernel(const __nv_bfloat16* __restrict__ A, const __nv_bfloat16* __restrict__ Bt,
                     float* __restrict__ C, int M, int Nt, int KH) {
    extern __shared__ char dsm[];
    const int KTt = KH / BK;          // k-tiles per term
    const int KT  = 3 * KTt;
    const int strideA = 2 * KH;
    const int strideB = 3 * KH;
    const int tid  = threadIdx.x;
    const int lane = tid & 31, wid = tid >> 5;
    const int wm = (wid & 3) * 32;
    const int wn = (wid >> 2) * 64;
    const int m0 = blockIdx.y * 128;
    const int n0 = blockIdx.x * 128;
    const uint32_t sbase = smem_u32(dsm);

    int v0 = tid, v1 = tid + 256;
    int ar0 = v0 >> 2, ac0 = v0 & 3;
    int ar1 = v1 >> 2, ac1 = v1 & 3;
    bool p0 = (m0 + ar0) < M, p1 = (m0 + ar1) < M;
    int cm0 = p0 ? (m0 + ar0) : 0, cm1 = p1 ? (m0 + ar1) : 0;

    float c[2][8][4];
    #pragma unroll
    for (int i = 0; i < 2; i++)
        #pragma unroll
        for (int j = 0; j < 8; j++)
            #pragma unroll
            for (int q = 0; q < 4; q++) c[i][j][q] = 0.f;

    auto issue = [&](int kt) {
        uint32_t da = sbase + (uint32_t)(kt & 3) * STG_B;
        uint32_t db = da + 128 * SROWB;
        int term = kt / KTt, kk = kt - term * KTt;
        int ka = kk * BK + (term == 1 ? KH : 0);   // term 0,2 -> hi block; term 1 -> lo
        int kb = kt * BK;
        cp16(da + (uint32_t)(ar0 * 80 + ac0 * 16), A + (size_t)cm0 * strideA + ka + ac0 * 8, p0);
        cp16(da + (uint32_t)(ar1 * 80 + ac1 * 16), A + (size_t)cm1 * strideA + ka + ac1 * 8, p1);
        cp16(db + (uint32_t)(ar0 * 80 + ac0 * 16), Bt + (size_t)(n0 + ar0) * strideB + kb + ac0 * 8, true);
        cp16(db + (uint32_t)(ar1 * 80 + ac1 * 16), Bt + (size_t)(n0 + ar1) * strideB + kb + ac1 * 8, true);
        asm volatile("cp.async.commit_group;");
    };

    issue(0); issue(1); issue(2);
    for (int kt = 0; kt < KT; kt++) {
        if (kt + 3 < KT) {
            issue(kt + 3);
            asm volatile("cp.async.wait_group 3;");
        } else {
            asm volatile("cp.async.wait_group 0;");
        }
        __syncthreads();

        uint32_t da = sbase + (uint32_t)(kt & 3) * STG_B;
        uint32_t db = da + 128 * SROWB;
        #pragma unroll
        for (int ks = 0; ks < 2; ks++) {
            uint32_t a[2][4], b[4][4];
            #pragma unroll
            for (int mi = 0; mi < 2; mi++) {
                uint32_t addr = da + (uint32_t)((wm + mi * 16 + (lane & 15)) * 80
                                              + (ks * 16 + (lane >> 4) * 8) * 2);
                ldm_x4(a[mi], addr);
            }
            #pragma unroll
            for (int ni = 0; ni < 4; ni++) {
                uint32_t addr = db + (uint32_t)((wn + ni * 16 + ((lane >> 4) << 3) + (lane & 7)) * 80
                                              + (ks * 16 + ((lane >> 3) & 1) * 8) * 2);
                ldm_x4(b[ni], addr);
            }
            #pragma unroll
            for (int mi = 0; mi < 2; mi++)
                #pragma unroll
                for (int nj = 0; nj < 8; nj++)
                    mma16816(c[mi][nj], a[mi], b[nj >> 1][(nj & 1) * 2 + 0],
                             b[nj >> 1][(nj & 1) * 2 + 1]);
        }
        __syncthreads();
    }

    #pragma unroll
    for (int mi = 0; mi < 2; mi++) {
        int gm = m0 + wm + mi * 16 + (lane >> 2);
        #pragma unroll
        for (int nj = 0; nj < 8; nj++) {
            int gn = n0 + wn + nj * 8 + (lane & 3) * 2;
            if (gm < M)
                *reinterpret_cast<float2*>(C + (size_t)gm * Nt + gn) =
                    make_float2(c[mi][nj][0], c[mi][nj][1]);
            if (gm + 8 < M)
                *reinterpret_cast<float2*>(C + (size_t)(gm + 8) * Nt + gn) =
                    make_float2(c[mi][nj][2], c[mi][nj][3]);
        }
    }
}

// ---------------- attention scores ----------------
__global__ void scores_kernel(const float* __restrict__ h, const float* __restrict__ asr,
                              const float* __restrict__ ads, int C) {
    int gw = (blockIdx.x * blockDim.x + threadIdx.x) >> 5;
    int lane = threadIdx.x & 31;
    if (gw >= NN * H) return;
    int n = gw / H, hh = gw % H;
    const float* hp = h + (size_t)n * H * C + (size_t)hh * C;
    const float* a1 = asr + hh * C;
    const float* a2 = ads + hh * C;
    float s1 = 0.f, s2 = 0.f;
    for (int c = lane; c < C; c += 32) {
        float v = hp[c];
        s1 += v * a1[c];
        s2 += v * a2[c];
    }
    #pragma unroll
    for (int o = 16; o; o >>= 1) {
        s1 += __shfl_down_sync(0xffffffffu, s1, o);
        s2 += __shfl_down_sync(0xffffffffu, s2, o);
    }
    if (lane == 0) { g_ssrc[gw] = s1; g_sdst[gw] = s2; }
}
__global__ void score1_kernel(const float* __restrict__ hbn0) {
    __shared__ float sws[H * 256];
    __shared__ float swd[H * 256];
    int tid = threadIdx.x;
    for (int i = tid; i < 2048; i += 256) {
        int k = i >> 3, hh = i & 7;
        sws[hh * 256 + k] = g_wsrc[i];
        swd[hh * 256 + k] = g_wdst[i];
    }
    __syncthreads();
    int w = tid >> 5, lane = tid & 31;
    int n = blockIdx.x * 8 + w;
    if (n >= NN) return;
    float v[8];
    #pragma unroll
    for (int j = 0; j < 8; j++) v[j] = hbn0[(size_t)n * 256 + j * 32 + lane];
    #pragma unroll
    for (int hh = 0; hh < H; hh++) {
        float s1 = 0.f, s2 = 0.f;
        #pragma unroll
        for (int j = 0; j < 8; j++) {
            int k = j * 32 + lane;
            s1 += v[j] * sws[hh * 256 + k];
            s2 += v[j] * swd[hh * 256 + k];
        }
        #pragma unroll
        for (int o = 16; o; o >>= 1) {
            s1 += __shfl_down_sync(0xffffffffu, s1, o);
            s2 += __shfl_down_sync(0xffffffffu, s2, o);
        }
        if (lane == 0) { g_ssrc[n * 8 + hh] = s1; g_sdst[n * 8 + hh] = s2; }
    }
}

// ---------------- fused softmax + aggregation (block per dst, sorted edges) ----------------
#define CH 32
struct SmaxSh {
    unsigned m[H];
    float den[H], rd[H], sdst[H], mf[H];
    int   srcs[CH];
    float al[CH][H];
};
template <int LAYER>
__global__ void fused_agg_kernel(const int* __restrict__ ei, const float* __restrict__ feat) {
    __shared__ SmaxSh sh;
    const int d = blockIdx.x, t = threadIdx.x;
    const int e0 = g_start[d];
    const int cnt = g_start[d + 1] - e0;

    if (t < H) { sh.m[t] = 0u; sh.den[t] = 0.f; sh.sdst[t] = g_sdst[d * H + t]; }
    __syncthreads();

    for (int idx = t; idx < cnt * H; idx += 256) {
        int el = idx >> 3, hh = idx & 7;
        int s = edge_src(ei, g_sorted[e0 + el]);
        float sc = g_ssrc[s * H + hh] + sh.sdst[hh];
        sc = sc > 0.f ? sc : 0.2f * sc;
        atomicMax(&sh.m[hh], fflip(sc));
    }
    __syncthreads();
    if (t < H) sh.mf[t] = funflip(sh.m[t]);
    __syncthreads();
    for (int idx = t; idx < cnt * H; idx += 256) {
        int el = idx >> 3, hh = idx & 7;
        int s = edge_src(ei, g_sorted[e0 + el]);
        float sc = g_ssrc[s * H + hh] + sh.sdst[hh];
        sc = sc > 0.f ? sc : 0.2f * sc;
        atomicAdd(&sh.den[hh], expf(sc - sh.mf[hh]));
    }
    __syncthreads();
    if (t < H) sh.rd[t] = 1.f / sh.den[t];
    __syncthreads();

    float acc0 = 0.f;
    float acc1[H] = {0.f, 0.f, 0.f, 0.f, 0.f, 0.f, 0.f, 0.f};

    for (int c0 = 0; c0 < cnt; c0 += CH) {
        int ce = min(CH, cnt - c0);
        if (t < ce * H) {
            int el = t >> 3, hh = t & 7;
            int s = edge_src(ei, g_sorted[e0 + c0 + el]);
            float sc = g_ssrc[s * H + hh] + sh.sdst[hh];
            sc = sc > 0.f ? sc : 0.2f * sc;
            sh.al[el][hh] = expf(sc - sh.mf[hh]) * sh.rd[hh];
            if (hh == 0) sh.srcs[el] = s;
        }
        __syncthreads();
        for (int j = 0; j < ce; j++) {
            float v = feat[(size_t)sh.srcs[j] * 256 + t];
            if (LAYER == 0) {
                acc0 += sh.al[j][t >> 5] * v;
            } else {
                #pragma unroll
                for (int hh = 0; hh < H; hh++) acc1[hh] += sh.al[j][hh] * v;
            }
        }
        __syncthreads();
    }

    if (LAYER == 0) {
        g_acc[(size_t)d * 256 + t] = acc0;
    } else {
        // dedup split write: [hi(2048) | lo(2048)]
        __nv_bfloat16* p = g_a1sp + (size_t)d * 4096;
        #pragma unroll
        for (int hh = 0; hh < H; hh++) {
            float y = acc1[hh];
            __nv_bfloat16 h = __float2bfloat16(y);
            __nv_bfloat16 l = __float2bfloat16(y - __bfloat162float(h));
            int j = hh * 256 + t;
            p[j] = h; p[2048 + j] = l;
        }
    }
}

// ---------------- batch norm ----------------
__global__ void zero_bn_kernel() {
    int i = threadIdx.x;
    g_bnsum[i] = 0.f; g_bnsq[i] = 0.f;
}
__global__ void bn_stats_kernel(const float* __restrict__ bias, float scale) {
    int c = threadIdx.x;
    float b = bias[c];
    int r0 = blockIdx.x * 50;
    int r1 = r0 + 50; if (r1 > NN) r1 = NN;
    float s = 0.f, q = 0.f;
    for (int r = r0; r < r1; r++) {
        float v = g_acc[(size_t)r * HID + c] * scale + b;
        s += v; q += v * v;
    }
    atomicAdd(&g_bnsum[c], s);
    atomicAdd(&g_bnsq[c], q);
}
// out_fp32 (optional) and/or dedup bf16 split (optional, row stride 512)
__global__ void bn_apply_kernel(const float* __restrict__ bias, float scale,
                                const float* __restrict__ gma, const float* __restrict__ bet,
                                const float* __restrict__ resid, float* __restrict__ out,
                                __nv_bfloat16* __restrict__ asp) {
    size_t i = (size_t)blockIdx.x * blockDim.x + threadIdx.x;
    if (i >= (size_t)NN * HID) return;
    int c = (int)(i & 255);
    float v = g_acc[i] * scale + bias[c];
    float mu = g_bnsum[c] * (1.0f / NN);
    float var = g_bnsq[c] * (1.0f / NN) - mu * mu;
    float y = gma[c] * (v - mu) * rsqrtf(var + EPSV) + bet[c];
    y = y > 0.f ? y : expm1f(y);
    if (resid) y += resid[i];
    if (out) out[i] = y;
    if (asp) {
        size_t r = i >> 8;
        __nv_bfloat16 h = __float2bfloat16(y);
        __nv_bfloat16 l = __float2bfloat16(y - __bfloat162float(h));
        __nv_bfloat16* p = asp + r * 512;
        p[c] = h; p[256 + c] = l;
    }
}

// ---------------- classifier output copy (+bias) ----------------
__global__ void out_copy_kernel(const float* __restrict__ scr, const float* __restrict__ bc,
                                float* __restrict__ out) {
    int i = blockIdx.x * blockDim.x + threadIdx.x;
    if (i >= NN * NC) return;
    int n = i / NC, c = i - n * NC;
    out[i] = scr[(size_t)n * 128 + c] + bc[c];
}

// ---------------- launch ----------------
extern "C" void kernel_launch(void* const* d_in, const int* in_sizes, int n_in,
                              void* d_out, int out_size) {
    const float* x   = (const float*)d_in[0];
    const int*   ei  = (const int*)  d_in[1];
    const float* W0  = (const float*)d_in[2];
    const float* as0 = (const float*)d_in[3];
    const float* ad0 = (const float*)d_in[4];
    const float* b0  = (const float*)d_in[5];
    const float* gm0 = (const float*)d_in[6];
    const float* be0 = (const float*)d_in[7];
    const float* W1  = (const float*)d_in[8];
    const float* as1 = (const float*)d_in[9];
    const float* ad1 = (const float*)d_in[10];
    const float* b1  = (const float*)d_in[11];
    const float* gm1 = (const float*)d_in[12];
    const float* be1 = (const float*)d_in[13];
    const float* Wc  = (const float*)d_in[14];
    const float* bc  = (const float*)d_in[15];
    float* out = (float*)d_out;

    float *h0, *hbn0, *acc;
    __nv_bfloat16 *xsp, *a1sp, *c1sp, *w0sp, *w1sp, *wcsp;
    cudaGetSymbolAddress((void**)&h0,   g_h0);
    cudaGetSymbolAddress((void**)&hbn0, g_hbn0);
    cudaGetSymbolAddress((void**)&acc,  g_acc);
    cudaGetSymbolAddress((void**)&xsp,  g_xsp);
    cudaGetSymbolAddress((void**)&a1sp, g_a1sp);
    cudaGetSymbolAddress((void**)&c1sp, g_c1sp);
    cudaGetSymbolAddress((void**)&w0sp, g_w0sp);
    cudaGetSymbolAddress((void**)&w1sp, g_w1sp);
    cudaGetSymbolAddress((void**)&wcsp, g_wcsp);

    cudaFuncSetAttribute(mma_gemm_kernel,
                         cudaFuncAttributeMaxDynamicSharedMemorySize, GSMEM);

    const int TB = 256;
    const int gNH32 = (NN * H * 32 + TB - 1) / TB;
    const int gNF   = (NN * HID + TB - 1) / TB;
    const int gET   = (ET + TB - 1) / TB;
    const int MT    = (NN + 127) / 128;

    // ===== operand prep =====
    split_a_kernel<<<(NN * 256 + TB - 1) / TB, TB>>>(x, xsp, NN);
    split_bT_kernel<<<(256 * 256 + TB - 1) / TB, TB>>>(W0, w0sp, 256);
    split_b1_kernel<<<(256 * 2048 + TB - 1) / TB, TB>>>(W1);
    split_bc_kernel<<<(128 * 256 + TB - 1) / TB, TB>>>(Wc);
    watt_kernel<<<(256 * H * 32 + TB - 1) / TB, TB>>>(W1, as1, ad1);

    // ===== edge sort by dst =====
    zero_cnt_kernel<<<(NN + TB - 1) / TB, TB>>>();
    hist_kernel<<<gET, TB>>>(ei);
    scan_kernel<<<1, 1024>>>();
    scatter_kernel<<<gET, TB>>>(ei);

    // ===== layer 0 =====
    {
        dim3 g(2, MT);
        mma_gemm_kernel<<<g, 256, GSMEM>>>(xsp, w0sp, h0, NN, 256, 256);
    }
    scores_kernel<<<gNH32, TB>>>(h0, as0, ad0, 32);
    fused_agg_kernel<0><<<NN, TB>>>(ei, h0);
    zero_bn_kernel<<<1, HID>>>();
    bn_stats_kernel<<<(NN + 49) / 50, HID>>>(b0, 1.0f);
    bn_apply_kernel<<<gNF, TB>>>(b0, 1.0f, gm0, be0, nullptr, hbn0, nullptr);

    // ===== layer 1 (projection commuted past aggregation) =====
    score1_kernel<<<(NN + 7) / 8, TB>>>(hbn0);
    fused_agg_kernel<1><<<NN, TB>>>(ei, hbn0);
    {
        dim3 g(2, MT);
        mma_gemm_kernel<<<g, 256, GSMEM>>>(a1sp, w1sp, acc, NN, 256, 2048);
    }
    zero_bn_kernel<<<1, HID>>>();
    bn_stats_kernel<<<(NN + 49) / 50, HID>>>(b1, 0.125f);
    bn_apply_kernel<<<gNF, TB>>>(b1, 0.125f, gm1, be1, hbn0, nullptr, c1sp);

    // ===== classifier (bf16-split mma into 128-wide scratch, then +bias copy) =====
    {
        dim3 g(1, MT);
        mma_gemm_kernel<<<g, 256, GSMEM>>>(c1sp, wcsp, h0, NN, 128, 256);
    }
    out_copy_kernel<<<(NN * NC + TB - 1) / TB, TB>>>(h0, bc, out);
}